// round 1
// baseline (speedup 1.0000x reference)
#include <cuda_runtime.h>

// EmergentNeuralNetwork: out = tanh(h_star @ w_ho - 0.5)
// h_star[:, j<3]  = tanh(x @ w_in[:, j] - thr_h[j])
// h_star[:, j>=3] = tanh(-thr_h[j])   (batch-constant -> folded into base[o])
//
// Inputs (metadata order):
//   d_in[0] x     float32 [8192, 4096]
//   d_in[1] w_in  float32 [4096, 3]
//   d_in[2] w_ho  float32 [64, 8]
//   d_in[3] thr_h float32 [64]
// Output: float32 [8192, 8]

#define TPB 256
#define ROWS_PER_BLOCK 8
#define COLS 4096
#define BATCH 8192
#define OUTS 8

__global__ __launch_bounds__(TPB)
void enn_kernel(const float* __restrict__ x,
                const float* __restrict__ w_in,
                const float* __restrict__ w_ho,
                const float* __restrict__ thr_h,
                float* __restrict__ out)
{
    __shared__ float s_part[8][3];   // per-warp partial sums (8 warps x 3 hidden)
    __shared__ float s_base[OUTS];   // folded bias for the 61 disconnected hiddens

    const int t    = threadIdx.x;
    const int warp = t >> 5;
    const int lane = t & 31;

    // --- threads 0..7: compute base[o] = sum_{j=3..63} tanh(-thr_h[j])*w_ho[j,o] - 0.5
    if (t < OUTS) {
        float b = -0.5f;
        #pragma unroll 1
        for (int j = 3; j < 64; j++)
            b = fmaf(tanhf(-thr_h[j]), w_ho[j * OUTS + t], b);
        s_base[t] = b;
    }

    // --- cache this thread's 16 columns of w_in (48 floats) in registers.
    // cols: {c*1024 + 4t .. +3} for c in 0..3.  w_in row-major [4096,3]:
    // 12 consecutive floats per 4-col group, 16B-aligned (col%4==0 -> 48B offset).
    float4 wv[4][3];
    #pragma unroll
    for (int c = 0; c < 4; c++) {
        const int col = c * 1024 + t * 4;
        const float4* wp = reinterpret_cast<const float4*>(w_in + (size_t)col * 3);
        wv[c][0] = wp[0];
        wv[c][1] = wp[1];
        wv[c][2] = wp[2];
    }

    // epilogue constants for output lanes
    float wh0 = 0.f, wh1 = 0.f, wh2 = 0.f, th0 = 0.f, th1 = 0.f, th2 = 0.f;
    if (t < OUTS) {
        wh0 = w_ho[0 * OUTS + t];
        wh1 = w_ho[1 * OUTS + t];
        wh2 = w_ho[2 * OUTS + t];
        th0 = thr_h[0];
        th1 = thr_h[1];
        th2 = thr_h[2];
    }

    #pragma unroll 1
    for (int r = 0; r < ROWS_PER_BLOCK; r++) {
        const size_t row = (size_t)blockIdx.x * ROWS_PER_BLOCK + r;
        const float4* xp = reinterpret_cast<const float4*>(x + row * COLS);

        float a0 = 0.f, a1 = 0.f, a2 = 0.f;
        #pragma unroll
        for (int c = 0; c < 4; c++) {
            const float4 xv = __ldcs(&xp[c * 256 + t]);   // streaming: x has no reuse
            const float4 w0 = wv[c][0], w1 = wv[c][1], w2 = wv[c][2];
            // element e of the 12-float group maps to (col + e/3, j = e%3)
            a0 = fmaf(xv.x, w0.x, a0);
            a1 = fmaf(xv.x, w0.y, a1);
            a2 = fmaf(xv.x, w0.z, a2);
            a0 = fmaf(xv.y, w0.w, a0);
            a1 = fmaf(xv.y, w1.x, a1);
            a2 = fmaf(xv.y, w1.y, a2);
            a0 = fmaf(xv.z, w1.z, a0);
            a1 = fmaf(xv.z, w1.w, a1);
            a2 = fmaf(xv.z, w2.x, a2);
            a0 = fmaf(xv.w, w2.y, a0);
            a1 = fmaf(xv.w, w2.z, a1);
            a2 = fmaf(xv.w, w2.w, a2);
        }

        // warp tree-reduce the 3 partials
        #pragma unroll
        for (int off = 16; off > 0; off >>= 1) {
            a0 += __shfl_xor_sync(0xFFFFFFFFu, a0, off);
            a1 += __shfl_xor_sync(0xFFFFFFFFu, a1, off);
            a2 += __shfl_xor_sync(0xFFFFFFFFu, a2, off);
        }
        if (lane == 0) {
            s_part[warp][0] = a0;
            s_part[warp][1] = a1;
            s_part[warp][2] = a2;
        }
        __syncthreads();

        if (t < OUTS) {
            float s0 = 0.f, s1 = 0.f, s2 = 0.f;
            #pragma unroll
            for (int w = 0; w < 8; w++) {
                s0 += s_part[w][0];
                s1 += s_part[w][1];
                s2 += s_part[w][2];
            }
            const float h0 = tanhf(s0 - th0);
            const float h1 = tanhf(s1 - th1);
            const float h2 = tanhf(s2 - th2);
            float o = s_base[t];
            o = fmaf(h0, wh0, o);
            o = fmaf(h1, wh1, o);
            o = fmaf(h2, wh2, o);
            out[row * OUTS + t] = tanhf(o);
        }
        __syncthreads();   // protect s_part before next row
    }
}

extern "C" void kernel_launch(void* const* d_in, const int* in_sizes, int n_in,
                              void* d_out, int out_size)
{
    const float* x     = (const float*)d_in[0];
    const float* w_in  = (const float*)d_in[1];
    const float* w_ho  = (const float*)d_in[2];
    const float* thr_h = (const float*)d_in[3];
    float* out = (float*)d_out;

    const int grid = BATCH / ROWS_PER_BLOCK;   // 1024
    enn_kernel<<<grid, TPB>>>(x, w_in, w_ho, thr_h, out);
}

// round 3
// speedup vs baseline: 1.5070x; 1.5070x over previous
#include <cuda_runtime.h>

// EmergentNeuralNetwork collapsed form: out = tanh(h_star @ w_ho - 0.5)
//   h_star[:, j<3]  = tanh(x @ w_in[:, j] - thr_h[j])
//   h_star[:, j>=3] = tanh(-thr_h[j])  (batch-constant -> folded into base[o])
//
// Inputs: x f32[8192,4096], w_in f32[4096,3], w_ho f32[64,8], thr_h f32[64]
// Output: f32[8192,8]

#define TPB 256
#define RPB 8          // rows per block, accumulated concurrently per thread
#define COLS 4096
#define BATCH 8192
#define OUTS 8

__global__ __launch_bounds__(TPB, 2)
void enn_kernel(const float* __restrict__ x,
                const float* __restrict__ w_in,
                const float* __restrict__ w_ho,
                const float* __restrict__ thr_h,
                float* __restrict__ out)
{
    __shared__ float s_part[8][RPB][3];  // [warp][row][hidden]
    __shared__ float s_base[OUTS];

    const int t    = threadIdx.x;
    const int warp = t >> 5;
    const int lane = t & 31;
    const size_t row0 = (size_t)blockIdx.x * RPB;

    // threads 0..7: base[o] = sum_{j=3..63} tanh(-thr_h[j])*w_ho[j,o] - 0.5
    if (t < OUTS) {
        float b = -0.5f;
        #pragma unroll 1
        for (int j = 3; j < 64; j++)
            b = fmaf(tanhf(-thr_h[j]), w_ho[j * OUTS + t], b);
        s_base[t] = b;
    }

    // hoist the w_in register cache (12 floats per column-group, 4 groups)
    float4 wreg[4][3];
    #pragma unroll
    for (int c = 0; c < 4; c++) {
        const int col = c * 1024 + t * 4;
        const float4* wp = reinterpret_cast<const float4*>(w_in + (size_t)col * 3);
        wreg[c][0] = __ldg(wp + 0);
        wreg[c][1] = __ldg(wp + 1);
        wreg[c][2] = __ldg(wp + 2);
    }

    // 24 accumulators: 8 rows x 3 hidden neurons
    float acc[RPB][3];
    #pragma unroll
    for (int r = 0; r < RPB; r++) {
        acc[r][0] = 0.f; acc[r][1] = 0.f; acc[r][2] = 0.f;
    }

    // thread t owns columns {c*1024 + 4t .. +3} for c in 0..3
    #pragma unroll
    for (int c = 0; c < 4; c++) {
        const float4 w0 = wreg[c][0], w1 = wreg[c][1], w2 = wreg[c][2];

        // batch 8 independent row loads (MLP)
        float4 xv[RPB];
        #pragma unroll
        for (int r = 0; r < RPB; r++)
            xv[r] = __ldcs(reinterpret_cast<const float4*>(x + (row0 + r) * COLS)
                           + c * 256 + t);

        #pragma unroll
        for (int r = 0; r < RPB; r++) {
            // 12-float w group maps: element e -> (col + e/3, hidden j = e%3)
            acc[r][0] = fmaf(xv[r].x, w0.x, acc[r][0]);
            acc[r][1] = fmaf(xv[r].x, w0.y, acc[r][1]);
            acc[r][2] = fmaf(xv[r].x, w0.z, acc[r][2]);
            acc[r][0] = fmaf(xv[r].y, w0.w, acc[r][0]);
            acc[r][1] = fmaf(xv[r].y, w1.x, acc[r][1]);
            acc[r][2] = fmaf(xv[r].y, w1.y, acc[r][2]);
            acc[r][0] = fmaf(xv[r].z, w1.z, acc[r][0]);
            acc[r][1] = fmaf(xv[r].z, w1.w, acc[r][1]);
            acc[r][2] = fmaf(xv[r].z, w2.x, acc[r][2]);
            acc[r][0] = fmaf(xv[r].w, w2.y, acc[r][0]);
            acc[r][1] = fmaf(xv[r].w, w2.z, acc[r][1]);
            acc[r][2] = fmaf(xv[r].w, w2.w, acc[r][2]);
        }
    }

    // single butterfly reduction over all 24 accumulators
    #pragma unroll
    for (int off = 16; off > 0; off >>= 1) {
        #pragma unroll
        for (int r = 0; r < RPB; r++) {
            acc[r][0] += __shfl_xor_sync(0xFFFFFFFFu, acc[r][0], off);
            acc[r][1] += __shfl_xor_sync(0xFFFFFFFFu, acc[r][1], off);
            acc[r][2] += __shfl_xor_sync(0xFFFFFFFFu, acc[r][2], off);
        }
    }
    if (lane == 0) {
        #pragma unroll
        for (int r = 0; r < RPB; r++) {
            s_part[warp][r][0] = acc[r][0];
            s_part[warp][r][1] = acc[r][1];
            s_part[warp][r][2] = acc[r][2];
        }
    }
    __syncthreads();

    // 64 threads: one (row, output) pair each
    if (t < RPB * OUTS) {
        const int r = t >> 3;
        const int o = t & 7;
        float s0 = 0.f, s1 = 0.f, s2 = 0.f;
        #pragma unroll
        for (int w = 0; w < 8; w++) {
            s0 += s_part[w][r][0];
            s1 += s_part[w][r][1];
            s2 += s_part[w][r][2];
        }
        const float h0 = tanhf(s0 - thr_h[0]);
        const float h1 = tanhf(s1 - thr_h[1]);
        const float h2 = tanhf(s2 - thr_h[2]);
        float v = s_base[o];
        v = fmaf(h0, w_ho[0 * OUTS + o], v);
        v = fmaf(h1, w_ho[1 * OUTS + o], v);
        v = fmaf(h2, w_ho[2 * OUTS + o], v);
        out[(row0 + r) * OUTS + o] = tanhf(v);
    }
}

extern "C" void kernel_launch(void* const* d_in, const int* in_sizes, int n_in,
                              void* d_out, int out_size)
{
    const float* x     = (const float*)d_in[0];
    const float* w_in  = (const float*)d_in[1];
    const float* w_ho  = (const float*)d_in[2];
    const float* thr_h = (const float*)d_in[3];
    float* out = (float*)d_out;

    enn_kernel<<<BATCH / RPB, TPB>>>(x, w_in, w_ho, thr_h, out);
}

// round 4
// speedup vs baseline: 1.5959x; 1.0589x over previous
#include <cuda_runtime.h>

// EmergentNeuralNetwork collapsed form: out = tanh(h_star @ w_ho - 0.5)
//   h_star[:, j<3]  = tanh(x @ w_in[:, j] - thr_h[j])
//   h_star[:, j>=3] = tanh(-thr_h[j])  (batch-constant, folded in epilogue)
//
// Inputs: x f32[8192,4096], w_in f32[4096,3], w_ho f32[64,8], thr_h f32[64]
// Output: f32[8192,8]

#define TPB 256
#define RPB 8          // rows per block, accumulated concurrently per thread
#define COLS 4096
#define BATCH 8192
#define OUTS 8

__global__ __launch_bounds__(TPB, 3)
void enn_kernel(const float* __restrict__ x,
                const float* __restrict__ w_in,
                const float* __restrict__ w_ho,
                const float* __restrict__ thr_h,
                float* __restrict__ out)
{
    __shared__ float s_part[8][RPB][3];  // [warp][row][hidden]
    __shared__ float s_tanh[61];         // tanh(-thr_h[j]) for j=3..63

    const int t    = threadIdx.x;
    const int warp = t >> 5;
    const int lane = t & 31;
    const size_t row0 = (size_t)blockIdx.x * RPB;

    // parallel precompute of the disconnected-hidden activations (1 tanh/thread)
    if (t < 61)
        s_tanh[t] = tanhf(-thr_h[t + 3]);

    // 24 accumulators: 8 rows x 3 hidden neurons
    float acc[RPB][3];
    #pragma unroll
    for (int r = 0; r < RPB; r++) {
        acc[r][0] = 0.f; acc[r][1] = 0.f; acc[r][2] = 0.f;
    }

    // thread t owns columns {c*1024 + 4t .. +3} for c in 0..3
    #pragma unroll
    for (int c = 0; c < 4; c++) {
        const int col = c * 1024 + t * 4;
        // transient 12-float w group (L2-hot; x streams via __ldcs so it
        // doesn't fight these for L1)
        const float4* wp = reinterpret_cast<const float4*>(w_in + (size_t)col * 3);
        const float4 w0 = __ldg(wp + 0);
        const float4 w1 = __ldg(wp + 1);
        const float4 w2 = __ldg(wp + 2);

        // batch 8 independent row loads (MLP)
        float4 xv[RPB];
        #pragma unroll
        for (int r = 0; r < RPB; r++)
            xv[r] = __ldcs(reinterpret_cast<const float4*>(x + (row0 + r) * COLS)
                           + c * 256 + t);

        #pragma unroll
        for (int r = 0; r < RPB; r++) {
            // 12-float w group maps: element e -> (col + e/3, hidden j = e%3)
            acc[r][0] = fmaf(xv[r].x, w0.x, acc[r][0]);
            acc[r][1] = fmaf(xv[r].x, w0.y, acc[r][1]);
            acc[r][2] = fmaf(xv[r].x, w0.z, acc[r][2]);
            acc[r][0] = fmaf(xv[r].y, w0.w, acc[r][0]);
            acc[r][1] = fmaf(xv[r].y, w1.x, acc[r][1]);
            acc[r][2] = fmaf(xv[r].y, w1.y, acc[r][2]);
            acc[r][0] = fmaf(xv[r].z, w1.z, acc[r][0]);
            acc[r][1] = fmaf(xv[r].z, w1.w, acc[r][1]);
            acc[r][2] = fmaf(xv[r].z, w2.x, acc[r][2]);
            acc[r][0] = fmaf(xv[r].w, w2.y, acc[r][0]);
            acc[r][1] = fmaf(xv[r].w, w2.z, acc[r][1]);
            acc[r][2] = fmaf(xv[r].w, w2.w, acc[r][2]);
        }
    }

    // single butterfly reduction over all 24 accumulators
    #pragma unroll
    for (int off = 16; off > 0; off >>= 1) {
        #pragma unroll
        for (int r = 0; r < RPB; r++) {
            acc[r][0] += __shfl_xor_sync(0xFFFFFFFFu, acc[r][0], off);
            acc[r][1] += __shfl_xor_sync(0xFFFFFFFFu, acc[r][1], off);
            acc[r][2] += __shfl_xor_sync(0xFFFFFFFFu, acc[r][2], off);
        }
    }
    if (lane == 0) {
        #pragma unroll
        for (int r = 0; r < RPB; r++) {
            s_part[warp][r][0] = acc[r][0];
            s_part[warp][r][1] = acc[r][1];
            s_part[warp][r][2] = acc[r][2];
        }
    }
    __syncthreads();

    // 64 threads: one (row, output) pair each
    if (t < RPB * OUTS) {
        const int r = t >> 3;
        const int o = t & 7;
        float s0 = 0.f, s1 = 0.f, s2 = 0.f;
        #pragma unroll
        for (int w = 0; w < 8; w++) {
            s0 += s_part[w][r][0];
            s1 += s_part[w][r][1];
            s2 += s_part[w][r][2];
        }
        // base[o]: contribution of the 61 disconnected hiddens
        float v = -0.5f;
        #pragma unroll 1
        for (int j = 0; j < 61; j++)
            v = fmaf(s_tanh[j], w_ho[(j + 3) * OUTS + o], v);
        const float h0 = tanhf(s0 - thr_h[0]);
        const float h1 = tanhf(s1 - thr_h[1]);
        const float h2 = tanhf(s2 - thr_h[2]);
        v = fmaf(h0, w_ho[0 * OUTS + o], v);
        v = fmaf(h1, w_ho[1 * OUTS + o], v);
        v = fmaf(h2, w_ho[2 * OUTS + o], v);
        out[(row0 + r) * OUTS + o] = tanhf(v);
    }
}

extern "C" void kernel_launch(void* const* d_in, const int* in_sizes, int n_in,
                              void* d_out, int out_size)
{
    const float* x     = (const float*)d_in[0];
    const float* w_in  = (const float*)d_in[1];
    const float* w_ho  = (const float*)d_in[2];
    const float* thr_h = (const float*)d_in[3];
    float* out = (float*)d_out;

    enn_kernel<<<BATCH / RPB, TPB>>>(x, w_in, w_ho, thr_h, out);
}